// round 4
// baseline (speedup 1.0000x reference)
#include <cuda_runtime.h>
#include <math_constants.h>

// Problem constants (fixed by the bench)
#define TRAJ  8
#define EVAL  30
#define NB    2048          // trajectories
#define NG    256           // groups = NB/TRAJ
#define WM    400           // nx
#define HM    400           // ny
#define DM    64            // nz
#define VOXF  0.2f
#define NPTS  (TRAJ * EVAL) // 240 points per group

// -------- persistent device scratch (no allocations allowed) --------
__device__ int g_mn0[NG][3];
__device__ int g_mx0[NG][3];

// sense-reversal global barrier state (replay-safe: count returns to 0 each
// use; gen increases monotonically -> identical behavior every replay)
__device__ unsigned g_count = 0;
__device__ unsigned g_gen   = 0;

__global__ void __launch_bounds__(256, 4)
kFused(const float* __restrict__ Df,
       const float* __restrict__ Dp,
       const float* __restrict__ L,
       const float* __restrict__ sdf,
       const float* __restrict__ minb,
       const float* __restrict__ shapes,
       const int*   __restrict__ map_id,
       float*       __restrict__ out)
{
    const int g   = blockIdx.x;
    const int tid = threadIdx.x;

    __shared__ float scoe[TRAJ][3][6];
    __shared__ float s_px[NPTS], s_py[NPTS], s_pz[NPTS];
    __shared__ float rmn[8][3], rmx[8][3];
    __shared__ int   s_span[3], s_shift[3];
    __shared__ int   s_wmn[3], s_wls[3];
    __shared__ float s_org[3];
    __shared__ float s_mb[3];
    __shared__ int   s_m;

    if (tid < 3) { s_span[tid] = 0; s_shift[tid] = 0; }

    // map id + map min-bound early (needed for prefetch prediction)
    if (tid == 0) s_m = map_id[g];
    __syncthreads();
    const int m = s_m;
    if (tid < 3) s_mb[tid] = minb[m * 3 + tid];

    // ---------------- Phase 1: coefficients + positions + group min/max ----
    if (tid < TRAJ * 3) {
        const int traj = tid / 3;
        const int c    = tid % 3;
        const int b    = g * TRAJ + traj;
        float d[6];
        #pragma unroll
        for (int s = 0; s < 3; s++) {
            d[s]     = Df[b * 9 + c * 3 + s];
            d[3 + s] = Dp[b * 9 + c * 3 + s];
        }
        #pragma unroll
        for (int j = 0; j < 6; j++) {
            float a = 0.f;
            #pragma unroll
            for (int k = 0; k < 6; k++) a += L[j * 6 + k] * d[k];
            scoe[traj][c][j] = a;
        }
    }
    __syncthreads();

    float mnx =  CUDART_INF_F, mny =  CUDART_INF_F, mnz =  CUDART_INF_F;
    float mxx = -CUDART_INF_F, mxy = -CUDART_INF_F, mxz = -CUDART_INF_F;

    if (tid < NPTS) {
        const int traj = tid / EVAL;
        const int n    = tid % EVAL;
        // linspace(dt, T, 30): step == dt exactly, so t = (n+1)*dt.
        const float t = (float)((double)(n + 1) * (2.0 / 30.0));
        float tp[6];
        tp[0] = 1.f;
        #pragma unroll
        for (int k = 1; k < 6; k++) tp[k] = tp[k - 1] * t;

        float p[3];
        #pragma unroll
        for (int c = 0; c < 3; c++) {
            float a = 0.f;
            #pragma unroll
            for (int k = 0; k < 6; k++) a += tp[k] * scoe[traj][c][k];
            p[c] = a;
        }
        s_px[tid] = p[0]; s_py[tid] = p[1]; s_pz[tid] = p[2];
        mnx = mxx = p[0];
        mny = mxy = p[1];
        mnz = mxz = p[2];

        // ---- Speculative L2 prefetch of the 8 trilinear corners ----------
        // Global corner index is (up to FP rounding) window-independent:
        // ig ~= floor((p - mb)/VOX). Prediction errors are harmless: this is
        // only a cache warm-up; the authoritative loads happen in Phase 3.
        {
            const int pgx = min(max((int)floorf(__fdiv_rn(p[0] - s_mb[0], VOXF)), 0), WM - 2);
            const int pgy = min(max((int)floorf(__fdiv_rn(p[1] - s_mb[1], VOXF)), 0), HM - 2);
            const int pgz = min(max((int)floorf(__fdiv_rn(p[2] - s_mb[2], VOXF)), 0), DM - 2);
            const float* base = sdf + ((size_t)m * DM) * HM * WM;
            #pragma unroll
            for (int dz = 0; dz < 2; dz++)
                #pragma unroll
                for (int dy = 0; dy < 2; dy++)
                    #pragma unroll
                    for (int dx = 0; dx < 2; dx++) {
                        const float* ptr =
                            base + ((size_t)(pgz + dz) * HM + (pgy + dy)) * WM + (pgx + dx);
                        asm volatile("prefetch.global.L2 [%0];" :: "l"(ptr));
                    }
        }
    }

    #pragma unroll
    for (int o = 16; o; o >>= 1) {
        mnx = fminf(mnx, __shfl_down_sync(0xffffffffu, mnx, o));
        mny = fminf(mny, __shfl_down_sync(0xffffffffu, mny, o));
        mnz = fminf(mnz, __shfl_down_sync(0xffffffffu, mnz, o));
        mxx = fmaxf(mxx, __shfl_down_sync(0xffffffffu, mxx, o));
        mxy = fmaxf(mxy, __shfl_down_sync(0xffffffffu, mxy, o));
        mxz = fmaxf(mxz, __shfl_down_sync(0xffffffffu, mxz, o));
    }
    if ((tid & 31) == 0) {
        const int w = tid >> 5;
        rmn[w][0] = mnx; rmn[w][1] = mny; rmn[w][2] = mnz;
        rmx[w][0] = mxx; rmx[w][1] = mxy; rmx[w][2] = mxz;
    }
    __syncthreads();

    if (tid == 0) {
        float fmn[3], fmx[3];
        #pragma unroll
        for (int c = 0; c < 3; c++) { fmn[c] = rmn[0][c]; fmx[c] = rmx[0][c]; }
        for (int w = 1; w < 8; w++) {
            #pragma unroll
            for (int c = 0; c < 3; c++) {
                fmn[c] = fminf(fmn[c], rmn[w][c]);
                fmx[c] = fmaxf(fmx[c], rmx[w][c]);
            }
        }
        #pragma unroll
        for (int c = 0; c < 3; c++) {
            const float mb = s_mb[c];
            // (int) cast == trunc toward zero, matching jnp.trunc().astype(int32)
            g_mn0[g][c] = (int)__fdiv_rn(fmn[c] - mb, VOXF);
            g_mx0[g][c] = (int)__fdiv_rn(fmx[c] - mb, VOXF);
        }
    }

    // ---------------- Global barrier (sense-reversal, replay-safe) ---------
    if (tid == 0) {
        __threadfence();
        const unsigned gen = *(volatile unsigned*)&g_gen;
        if (atomicAdd(&g_count, 1u) == (unsigned)gridDim.x - 1u) {
            g_count = 0;
            __threadfence();
            atomicAdd(&g_gen, 1u);
        } else {
            while (*(volatile unsigned*)&g_gen == gen) { }
        }
        __threadfence();
    }
    __syncthreads();

    // ---------------- Phase 2: redundant global reductions + window --------
    {
        // thread 'tid' handles group 'tid' (NG == blockDim.x)
        int mn[3], mx[3];
        #pragma unroll
        for (int c = 0; c < 3; c++) {
            mn[c] = g_mn0[tid][c];
            mx[c] = g_mx0[tid][c];
            atomicMax(&s_span[c], mx[c] - mn[c]);   // span >= 0 always
        }
        __syncthreads();

        const int m2 = map_id[tid];
        #pragma unroll
        for (int c = 0; c < 3; c++) {
            const int span = s_span[c];
            const int cc = (mn[c] + mx[c]) >> 1;    // Python floor-div by 2
            int a  = cc - (span >> 1) - 5;
            int bx = cc + (span >> 1) + 5;
            const int na = max(a, 0);
            bx += na - a; a = na;
            const int shp = (int)shapes[m2 * 3 + c];
            const int nb = min(bx, shp);
            a -= bx - nb; bx = nb;
            const int sh = (a < 0) ? -a : 0;
            atomicMax(&s_shift[c], sh);
        }
        __syncthreads();

        if (tid == 0) {
            #pragma unroll
            for (int c = 0; c < 3; c++) {
                const int mnc = g_mn0[g][c];
                const int mxc = g_mx0[g][c];
                const int span = s_span[c];
                const int cc = (mnc + mxc) >> 1;
                int a  = cc - (span >> 1) - 5;
                int bx = cc + (span >> 1) + 5;
                const int na = max(a, 0);
                bx += na - a; a = na;
                const int shp = (int)shapes[m * 3 + c];
                const int nb = min(bx, shp);
                a -= bx - nb; bx = nb;
                a += s_shift[c];
                s_wmn[c] = a;
                s_wls[c] = bx - a;
                s_org[c] = (float)a * VOXF + s_mb[c];
            }
        }
        __syncthreads();
    }

    // ---------------- Phase 3: trilinear gather + cost + warp sum ----------
    {
        const int warp = tid >> 5;          // trajectory within group
        const int lane = tid & 31;
        const int b    = g * TRAJ + warp;

        const int mnX = s_wmn[0], mnY = s_wmn[1], mnZ = s_wmn[2];
        const int lsX = s_wls[0], lsY = s_wls[1], lsZ = s_wls[2];
        const float ogX = s_org[0], ogY = s_org[1], ogZ = s_org[2];

        float contrib = 0.f;
        if (lane < EVAL) {
            const int idx = warp * EVAL + lane;
            const float px = s_px[idx], py = s_py[idx], pz = s_pz[idx];

            const float gx = __fdiv_rn(px - ogX, VOXF);
            const float gy = __fdiv_rn(py - ogY, VOXF);
            const float gz = __fdiv_rn(pz - ogZ, VOXF);

            const float gpx = __fdiv_rn(2.0f * gx, (float)(lsX - 1)) - 1.0f;
            const float gpy = __fdiv_rn(2.0f * gy, (float)(lsY - 1)) - 1.0f;
            const float gpz = __fdiv_rn(2.0f * gz, (float)(lsZ - 1)) - 1.0f;
            const bool valid = (gpx < 0.99f) && (gpx > -0.99f) &&
                               (gpy < 0.99f) && (gpy > -0.99f) &&
                               (gpz < 0.99f) && (gpz > -0.99f);

            const float flx = floorf(gx), fly = floorf(gy), flz = floorf(gz);
            const int l0x = (int)flx, l0y = (int)fly, l0z = (int)flz;
            const float fx = gx - flx, fy = gy - fly, fz = gz - flz;

            float acc = 0.f;
            #pragma unroll
            for (int dx = 0; dx < 2; dx++) {
                const int   ilx = l0x + dx;
                const float wx  = dx ? fx : (1.0f - fx);
                const bool  okx = (ilx >= 0) && (ilx < lsX);
                #pragma unroll
                for (int dy = 0; dy < 2; dy++) {
                    const int   ily = l0y + dy;
                    const float wy  = dy ? fy : (1.0f - fy);
                    const bool  oky = (ily >= 0) && (ily < lsY);
                    #pragma unroll
                    for (int dz = 0; dz < 2; dz++) {
                        const int   ilz = l0z + dz;
                        const float wz  = dz ? fz : (1.0f - fz);
                        const bool  okz = (ilz >= 0) && (ilz < lsZ);
                        if (okx && oky && okz) {
                            int igx = ilx + mnX;
                            int igy = ily + mnY;
                            int igz = ilz + mnZ;
                            igx = min(max(igx, 0), WM - 1);
                            igy = min(max(igy, 0), HM - 1);
                            igz = min(max(igz, 0), DM - 1);
                            const float val =
                                __ldg(&sdf[((m * DM + igz) * HM + igy) * WM + igx]);
                            acc += (wx * wy * wz) * val;
                        }
                    }
                }
            }
            const float e = __fdiv_rn(acc - 0.5f, 0.3f);
            const float cost = expf(-e);
            contrib = valid ? cost : 0.f;
        }

        #pragma unroll
        for (int o = 16; o; o >>= 1)
            contrib += __shfl_down_sync(0xffffffffu, contrib, o);

        if (lane == 0) out[b] = contrib * (float)(2.0 / 30.0);
    }
}

// ---------------------------------------------------------------
extern "C" void kernel_launch(void* const* d_in, const int* in_sizes, int n_in,
                              void* d_out, int out_size)
{
    const float* Df   = (const float*)d_in[0];
    const float* Dp   = (const float*)d_in[1];
    const float* L    = (const float*)d_in[2];
    const float* sdf  = (const float*)d_in[3];
    const float* minb = (const float*)d_in[4];
    const float* shp  = (const float*)d_in[5];
    const int*   mid  = (const int*)d_in[6];

    kFused<<<NG, 256>>>(Df, Dp, L, sdf, minb, shp, mid, (float*)d_out);
}

// round 5
// speedup vs baseline: 1.0652x; 1.0652x over previous
#include <cuda_runtime.h>
#include <math_constants.h>

// Problem constants (fixed by the bench)
#define TRAJ  8
#define EVAL  30
#define NB    2048          // trajectories
#define NG    256           // groups = NB/TRAJ
#define HALF  15            // evals per half-block
#define WM    400           // nx
#define HM    400           // ny
#define DM    64            // nz
#define VOXF  0.2f
#define NPTS  (TRAJ * EVAL) // 240 points per group
#define NBLK  (NG * 2)      // 512 blocks, 2 per group

// -------- persistent device scratch (no allocations allowed) --------
__device__ int g_mn0[NG][3];
__device__ int g_mx0[NG][3];

// sense-reversal global barrier state (replay-safe: count returns to 0 each
// use; gen increases monotonically -> identical behavior every replay)
__device__ unsigned g_count = 0;
__device__ unsigned g_gen   = 0;

__global__ void __launch_bounds__(256, 4)
kFused(const float* __restrict__ Df,
       const float* __restrict__ Dp,
       const float* __restrict__ L,
       const float* __restrict__ sdf,
       const float* __restrict__ minb,
       const float* __restrict__ shapes,
       const int*   __restrict__ map_id,
       float*       __restrict__ out)
{
    const int g    = blockIdx.x >> 1;     // group
    const int half = blockIdx.x & 1;      // eval-half handled in phase 3
    const int tid  = threadIdx.x;

    __shared__ float scoe[TRAJ][3][6];
    __shared__ float s_px[NPTS], s_py[NPTS], s_pz[NPTS];
    __shared__ float rmn[8][3], rmx[8][3];
    __shared__ int   s_span[3], s_shift[3];
    __shared__ int   s_wmn[3], s_wls[3];
    __shared__ float s_org[3];

    if (tid < 3) { s_span[tid] = 0; s_shift[tid] = 0; }

    // ---------------- Phase 1: coefficients + positions + group min/max ----
    // (both half-blocks compute positions redundantly; only half==0 publishes
    // bounds and zeroes the output slots)
    if (tid < TRAJ * 3) {
        const int traj = tid / 3;
        const int c    = tid % 3;
        const int b    = g * TRAJ + traj;
        float d[6];
        #pragma unroll
        for (int s = 0; s < 3; s++) {
            d[s]     = Df[b * 9 + c * 3 + s];
            d[3 + s] = Dp[b * 9 + c * 3 + s];
        }
        #pragma unroll
        for (int j = 0; j < 6; j++) {
            float a = 0.f;
            #pragma unroll
            for (int k = 0; k < 6; k++) a += L[j * 6 + k] * d[k];
            scoe[traj][c][j] = a;
        }
    }
    if (half == 0 && tid < TRAJ) out[g * TRAJ + tid] = 0.f;
    __syncthreads();

    float mnx =  CUDART_INF_F, mny =  CUDART_INF_F, mnz =  CUDART_INF_F;
    float mxx = -CUDART_INF_F, mxy = -CUDART_INF_F, mxz = -CUDART_INF_F;

    if (tid < NPTS) {
        const int traj = tid / EVAL;
        const int n    = tid % EVAL;
        // linspace(dt, T, 30): step == dt exactly, so t = (n+1)*dt.
        const float t = (float)((double)(n + 1) * (2.0 / 30.0));
        float tp[6];
        tp[0] = 1.f;
        #pragma unroll
        for (int k = 1; k < 6; k++) tp[k] = tp[k - 1] * t;

        float p[3];
        #pragma unroll
        for (int c = 0; c < 3; c++) {
            float a = 0.f;
            #pragma unroll
            for (int k = 0; k < 6; k++) a += tp[k] * scoe[traj][c][k];
            p[c] = a;
        }
        s_px[tid] = p[0]; s_py[tid] = p[1]; s_pz[tid] = p[2];
        mnx = mxx = p[0];
        mny = mxy = p[1];
        mnz = mxz = p[2];
    }

    #pragma unroll
    for (int o = 16; o; o >>= 1) {
        mnx = fminf(mnx, __shfl_down_sync(0xffffffffu, mnx, o));
        mny = fminf(mny, __shfl_down_sync(0xffffffffu, mny, o));
        mnz = fminf(mnz, __shfl_down_sync(0xffffffffu, mnz, o));
        mxx = fmaxf(mxx, __shfl_down_sync(0xffffffffu, mxx, o));
        mxy = fmaxf(mxy, __shfl_down_sync(0xffffffffu, mxy, o));
        mxz = fmaxf(mxz, __shfl_down_sync(0xffffffffu, mxz, o));
    }
    if ((tid & 31) == 0) {
        const int w = tid >> 5;
        rmn[w][0] = mnx; rmn[w][1] = mny; rmn[w][2] = mnz;
        rmx[w][0] = mxx; rmx[w][1] = mxy; rmx[w][2] = mxz;
    }
    __syncthreads();

    if (half == 0 && tid == 0) {
        float fmn[3], fmx[3];
        #pragma unroll
        for (int c = 0; c < 3; c++) { fmn[c] = rmn[0][c]; fmx[c] = rmx[0][c]; }
        for (int w = 1; w < 8; w++) {
            #pragma unroll
            for (int c = 0; c < 3; c++) {
                fmn[c] = fminf(fmn[c], rmn[w][c]);
                fmx[c] = fmaxf(fmx[c], rmx[w][c]);
            }
        }
        const int m = map_id[g];
        #pragma unroll
        for (int c = 0; c < 3; c++) {
            const float mb = minb[m * 3 + c];
            // (int) cast == trunc toward zero, matching jnp.trunc().astype(int32)
            g_mn0[g][c] = (int)__fdiv_rn(fmn[c] - mb, VOXF);
            g_mx0[g][c] = (int)__fdiv_rn(fmx[c] - mb, VOXF);
        }
    }

    // ---------------- Global barrier (sense-reversal, replay-safe) ---------
    if (tid == 0) {
        __threadfence();
        const unsigned gen = *(volatile unsigned*)&g_gen;
        if (atomicAdd(&g_count, 1u) == (unsigned)NBLK - 1u) {
            g_count = 0;
            __threadfence();
            atomicAdd(&g_gen, 1u);
        } else {
            while (*(volatile unsigned*)&g_gen == gen) { }
        }
        __threadfence();
    }
    __syncthreads();

    // ---------------- Phase 2: redundant global reductions + window --------
    {
        // thread 'tid' handles group 'tid' (NG == blockDim.x)
        int mn[3], mx[3];
        #pragma unroll
        for (int c = 0; c < 3; c++) {
            mn[c] = g_mn0[tid][c];
            mx[c] = g_mx0[tid][c];
            atomicMax(&s_span[c], mx[c] - mn[c]);   // span >= 0 always
        }
        __syncthreads();

        const int m2 = map_id[tid];
        #pragma unroll
        for (int c = 0; c < 3; c++) {
            const int span = s_span[c];
            const int cc = (mn[c] + mx[c]) >> 1;    // Python floor-div by 2
            int a  = cc - (span >> 1) - 5;
            int bx = cc + (span >> 1) + 5;
            const int na = max(a, 0);
            bx += na - a; a = na;
            const int shp = (int)shapes[m2 * 3 + c];
            const int nb = min(bx, shp);
            a -= bx - nb; bx = nb;
            const int sh = (a < 0) ? -a : 0;
            atomicMax(&s_shift[c], sh);
        }
        __syncthreads();

        if (tid == 0) {
            const int m = map_id[g];
            #pragma unroll
            for (int c = 0; c < 3; c++) {
                const int mnc = g_mn0[g][c];
                const int mxc = g_mx0[g][c];
                const int span = s_span[c];
                const int cc = (mnc + mxc) >> 1;
                int a  = cc - (span >> 1) - 5;
                int bx = cc + (span >> 1) + 5;
                const int na = max(a, 0);
                bx += na - a; a = na;
                const int shp = (int)shapes[m * 3 + c];
                const int nb = min(bx, shp);
                a -= bx - nb; bx = nb;
                a += s_shift[c];
                s_wmn[c] = a;
                s_wls[c] = bx - a;
                s_org[c] = (float)a * VOXF + minb[m * 3 + c];
            }
        }
        __syncthreads();
    }

    // ---------------- Phase 3: trilinear gather + cost + partial warp sum --
    // warp w handles trajectory w of this group; lanes 0..14 handle evals
    // half*15 + lane. The two half-blocks' partial sums combine via a single
    // commutative f32 atomicAdd each (deterministic: 2 contributions).
    {
        const int warp = tid >> 5;
        const int lane = tid & 31;
        const int b    = g * TRAJ + warp;

        const int m = map_id[g];
        const int mnX = s_wmn[0], mnY = s_wmn[1], mnZ = s_wmn[2];
        const int lsX = s_wls[0], lsY = s_wls[1], lsZ = s_wls[2];
        const float ogX = s_org[0], ogY = s_org[1], ogZ = s_org[2];

        float contrib = 0.f;
        if (lane < HALF) {
            const int ev  = half * HALF + lane;
            const int idx = warp * EVAL + ev;
            const float px = s_px[idx], py = s_py[idx], pz = s_pz[idx];

            const float gx = __fdiv_rn(px - ogX, VOXF);
            const float gy = __fdiv_rn(py - ogY, VOXF);
            const float gz = __fdiv_rn(pz - ogZ, VOXF);

            const float gpx = __fdiv_rn(2.0f * gx, (float)(lsX - 1)) - 1.0f;
            const float gpy = __fdiv_rn(2.0f * gy, (float)(lsY - 1)) - 1.0f;
            const float gpz = __fdiv_rn(2.0f * gz, (float)(lsZ - 1)) - 1.0f;
            const bool valid = (gpx < 0.99f) && (gpx > -0.99f) &&
                               (gpy < 0.99f) && (gpy > -0.99f) &&
                               (gpz < 0.99f) && (gpz > -0.99f);

            const float flx = floorf(gx), fly = floorf(gy), flz = floorf(gz);
            const int l0x = (int)flx, l0y = (int)fly, l0z = (int)flz;
            const float fx = gx - flx, fy = gy - fly, fz = gz - flz;

            float acc = 0.f;
            #pragma unroll
            for (int dx = 0; dx < 2; dx++) {
                const int   ilx = l0x + dx;
                const float wx  = dx ? fx : (1.0f - fx);
                const bool  okx = (ilx >= 0) && (ilx < lsX);
                #pragma unroll
                for (int dy = 0; dy < 2; dy++) {
                    const int   ily = l0y + dy;
                    const float wy  = dy ? fy : (1.0f - fy);
                    const bool  oky = (ily >= 0) && (ily < lsY);
                    #pragma unroll
                    for (int dz = 0; dz < 2; dz++) {
                        const int   ilz = l0z + dz;
                        const float wz  = dz ? fz : (1.0f - fz);
                        const bool  okz = (ilz >= 0) && (ilz < lsZ);
                        if (okx && oky && okz) {
                            int igx = ilx + mnX;
                            int igy = ily + mnY;
                            int igz = ilz + mnZ;
                            igx = min(max(igx, 0), WM - 1);
                            igy = min(max(igy, 0), HM - 1);
                            igz = min(max(igz, 0), DM - 1);
                            const float val =
                                __ldg(&sdf[((m * DM + igz) * HM + igy) * WM + igx]);
                            acc += (wx * wy * wz) * val;
                        }
                    }
                }
            }
            const float e = __fdiv_rn(acc - 0.5f, 0.3f);
            const float cost = expf(-e);
            contrib = valid ? cost : 0.f;
        }

        #pragma unroll
        for (int o = 16; o; o >>= 1)
            contrib += __shfl_down_sync(0xffffffffu, contrib, o);

        if (lane == 0)
            atomicAdd(&out[b], contrib * (float)(2.0 / 30.0));
    }
}

// ---------------------------------------------------------------
extern "C" void kernel_launch(void* const* d_in, const int* in_sizes, int n_in,
                              void* d_out, int out_size)
{
    const float* Df   = (const float*)d_in[0];
    const float* Dp   = (const float*)d_in[1];
    const float* L    = (const float*)d_in[2];
    const float* sdf  = (const float*)d_in[3];
    const float* minb = (const float*)d_in[4];
    const float* shp  = (const float*)d_in[5];
    const int*   mid  = (const int*)d_in[6];

    kFused<<<NBLK, 256>>>(Df, Dp, L, sdf, minb, shp, mid, (float*)d_out);
}